// round 16
// baseline (speedup 1.0000x reference)
#include <cuda_runtime.h>
#include <cstdint>

// ---------------- scratch (no allocations allowed) ----------------
#define MAX_BLOCKS 2048
__device__ float g_partials[MAX_BLOCKS];
__device__ unsigned int g_ticket = 0;   // last block wraps it back to 0
__device__ unsigned int g_ctr = 0;      // work-steal chunk counter; last block resets

#define CHUNK_PAIRS 64   // 128 edges per chunk: 2 int4 per lane, ~8 chunks/warp

// Warp-level dynamic work stealing with PREFETCHED grabs:
//  - lane 0 issues the atomicAdd for the NEXT chunk before the warp processes
//    the current one; the shfl that consumes it comes after ~2 gather round
//    trips, hiding the ~318cyc atomic latency entirely.
//  - 64-pair chunks -> ~8 chunks/warp: imbalance bounded at ~1 chunk (~12%)
//    instead of the R15 bug (2 chunks/warp -> 50% quantization imbalance).
//  - chunk = 2 int4 loads per lane (R4-proven 2-wide gather MLP).
__global__ void __launch_bounds__(256)
mde_steal_kernel(const float4* __restrict__ X,
                 const int4* __restrict__ epairs,
                 const float2* __restrict__ wpairs,
                 int npairs,
                 int nchunks,
                 const int2* __restrict__ etail,
                 const float* __restrict__ wtail,
                 int p,
                 float* __restrict__ out, float inv_p) {
    int tid  = threadIdx.x;
    int lane = tid & 31;
    int wid  = tid >> 5;
    float acc = 0.0f;

    // ---- dynamic chunk loop with prefetched grabs ----
    unsigned int cur;
    if (lane == 0) cur = atomicAdd(&g_ctr, 1u);
    cur = __shfl_sync(0xffffffffu, cur, 0);

    while (cur < (unsigned int)nchunks) {
        unsigned int nxt;
        if (lane == 0) nxt = atomicAdd(&g_ctr, 1u);   // issue early; consumed later

        int k0 = (int)cur * CHUNK_PAIRS + lane;       // first int4 of this lane
        int k1 = k0 + 32;                             // second int4
        bool v0 = (k0 < npairs);
        bool v1 = (k1 < npairs);

        int4   eA = v0 ? __ldcs(&epairs[k0]) : make_int4(0, 0, 0, 0);
        int4   eB = v1 ? __ldcs(&epairs[k1]) : make_int4(0, 0, 0, 0);
        float2 wA = v0 ? __ldcs(&wpairs[k0]) : make_float2(0.f, 0.f);
        float2 wB = v1 ? __ldcs(&wpairs[k1]) : make_float2(0.f, 0.f);

        float4 a0 = __ldg(&X[eA.x]);
        float4 b0 = __ldg(&X[eA.y]);
        float4 a1 = __ldg(&X[eA.z]);
        float4 b1 = __ldg(&X[eA.w]);
        float4 a2 = __ldg(&X[eB.x]);
        float4 b2 = __ldg(&X[eB.y]);
        float4 a3 = __ldg(&X[eB.z]);
        float4 b3 = __ldg(&X[eB.w]);

        float dx0 = a0.x - b0.x, dy0 = a0.y - b0.y, dz0 = a0.z - b0.z, dw0 = a0.w - b0.w;
        float dx1 = a1.x - b1.x, dy1 = a1.y - b1.y, dz1 = a1.z - b1.z, dw1 = a1.w - b1.w;
        float dx2 = a2.x - b2.x, dy2 = a2.y - b2.y, dz2 = a2.z - b2.z, dw2 = a2.w - b2.w;
        float dx3 = a3.x - b3.x, dy3 = a3.y - b3.y, dz3 = a3.z - b3.z, dw3 = a3.w - b3.w;
        acc = fmaf(wA.x, dx0 * dx0 + dy0 * dy0 + dz0 * dz0 + dw0 * dw0, acc);
        acc = fmaf(wA.y, dx1 * dx1 + dy1 * dy1 + dz1 * dz1 + dw1 * dw1, acc);
        acc = fmaf(wB.x, dx2 * dx2 + dy2 * dy2 + dz2 * dz2 + dw2 * dw2, acc);
        acc = fmaf(wB.y, dx3 * dx3 + dy3 * dy3 + dz3 * dz3 + dw3 * dw3, acc);

        cur = __shfl_sync(0xffffffffu, nxt, 0);       // atomic latency now hidden
    }

    // ---- single-edge tail (p odd; at most 1 edge) ----
    int t = blockIdx.x * blockDim.x + tid;
    int stride = gridDim.x * blockDim.x;
    for (int k = npairs * 2 + t; k < p; k += stride) {
        int2 e = __ldg(&etail[k]);
        float4 a = __ldg(&X[e.x]);
        float4 b = __ldg(&X[e.y]);
        float dx = a.x - b.x, dy = a.y - b.y, dz = a.z - b.z, dw = a.w - b.w;
        acc = fmaf(__ldg(&wtail[k]), dx * dx + dy * dy + dz * dz + dw * dw, acc);
    }

    // ---- fused reduction ----
    #pragma unroll
    for (int off = 16; off > 0; off >>= 1)
        acc += __shfl_down_sync(0xffffffffu, acc, off);

    __shared__ float warp_sums[8];
    if (lane == 0) warp_sums[wid] = acc;
    __syncthreads();

    __shared__ bool is_last;
    if (wid == 0) {
        float v = (lane < 8) ? warp_sums[lane] : 0.0f;
        #pragma unroll
        for (int off = 4; off > 0; off >>= 1)
            v += __shfl_down_sync(0xffffffffu, v, off);
        if (lane == 0) {
            g_partials[blockIdx.x] = v;
            __threadfence();
            unsigned int done = atomicInc(&g_ticket, gridDim.x - 1);
            is_last = (done == gridDim.x - 1);   // wraps ticket back to 0
        }
    }
    __syncthreads();

    if (is_last) {
        if (tid == 0) g_ctr = 0;   // all grabs done before any ticket arrives
        double s = 0.0;
        for (int i = tid; i < (int)gridDim.x; i += blockDim.x)
            s += (double)g_partials[i];
        __shared__ double dsums[8];
        #pragma unroll
        for (int off = 16; off > 0; off >>= 1)
            s += __shfl_down_sync(0xffffffffu, s, off);
        if (lane == 0) dsums[wid] = s;
        __syncthreads();
        if (wid == 0) {
            double v = (lane < 8) ? dsums[lane] : 0.0;
            #pragma unroll
            for (int off = 4; off > 0; off >>= 1)
                v += __shfl_down_sync(0xffffffffu, v, off);
            if (lane == 0)
                out[0] = (float)(v * (double)inv_p);
        }
    }
}

extern "C" void kernel_launch(void* const* d_in, const int* in_sizes, int n_in,
                              void* d_out, int out_size) {
    // Inputs: X (f32, 1M x 4), edges (int32, 10M x 2), weights (f32, 10M)
    const float4* X     = (const float4*)d_in[0];
    const int*    edges = (const int*)d_in[1];
    const float*  w     = (const float*)d_in[2];
    float*        out   = (float*)d_out;

    int p = in_sizes[2];
    int npairs = p / 2;
    int nchunks = (npairs + CHUNK_PAIRS - 1) / CHUNK_PAIRS;

    int blocks = 1184;   // 148 SMs x 8 CTAs, 64 warps/SM (L1tex-ceiling config)
    if (blocks > MAX_BLOCKS) blocks = MAX_BLOCKS;

    mde_steal_kernel<<<blocks, 256>>>(X,
                                      (const int4*)edges, (const float2*)w,
                                      npairs, nchunks,
                                      (const int2*)edges, w, p,
                                      out, 1.0f / (float)p);
}

// round 17
// speedup vs baseline: 1.3299x; 1.3299x over previous
#include <cuda_runtime.h>
#include <cstdint>

// ---------------- scratch (no allocations allowed) ----------------
#define MAX_BLOCKS 8192
__device__ float g_partials[MAX_BLOCKS];
__device__ unsigned int g_ticket = 0;   // last block wraps it back to 0

// Fused single-kernel MDE, multi-wave launch:
//  - proven grid-stride loop (R3/R8 body): one int4 (2 edges) + float2 weights
//    per thread per iteration, 4 independent float4 gathers in flight.
//  - ~4 waves of CTAs: early-finishing CTAs hand their SM slot to queued CTAs,
//    amortizing the B300 cross-CTA L1tex-queue completion spread (spr~1.1-1.3
//    at MLP_p1~4/occ8) to a fraction of one wave. (R2's 4883-block main kernel
//    measured ~74us vs 79.9us for the same body at 1184 blocks.)
//  - fused reduction: block partials + ticket; last block reduces and writes
//    the mean; atomicInc wrap resets the ticket (deterministic graph replays).
__global__ void __launch_bounds__(256)
mde_fused_kernel(const float4* __restrict__ X,
                 const int4* __restrict__ epairs,   // 2 edges per element
                 const float2* __restrict__ wpairs, // 2 weights per element
                 int npairs,
                 const int2* __restrict__ etail,    // leftover single edge view
                 const float* __restrict__ wtail,
                 int p,                             // total edges
                 float* __restrict__ out,
                 float inv_p) {
    float acc = 0.0f;
    int stride = gridDim.x * blockDim.x;
    int tid = blockIdx.x * blockDim.x + threadIdx.x;

    for (int k = tid; k < npairs; k += stride) {
        int4   e = __ldcs(&epairs[k]);
        float2 w = __ldcs(&wpairs[k]);
        float4 a0 = __ldg(&X[e.x]);
        float4 b0 = __ldg(&X[e.y]);
        float4 a1 = __ldg(&X[e.z]);
        float4 b1 = __ldg(&X[e.w]);
        float dx0 = a0.x - b0.x, dy0 = a0.y - b0.y, dz0 = a0.z - b0.z, dw0 = a0.w - b0.w;
        float dx1 = a1.x - b1.x, dy1 = a1.y - b1.y, dz1 = a1.z - b1.z, dw1 = a1.w - b1.w;
        acc = fmaf(w.x, dx0 * dx0 + dy0 * dy0 + dz0 * dz0 + dw0 * dw0, acc);
        acc = fmaf(w.y, dx1 * dx1 + dy1 * dy1 + dz1 * dz1 + dw1 * dw1, acc);
    }

    // Tail edge (p odd; at most 1).
    int tail_base = npairs * 2;
    for (int k = tail_base + tid; k < p; k += stride) {
        int2 e = __ldg(&etail[k]);
        float4 a = __ldg(&X[e.x]);
        float4 b = __ldg(&X[e.y]);
        float dx = a.x - b.x, dy = a.y - b.y, dz = a.z - b.z, dw = a.w - b.w;
        acc = fmaf(__ldg(&wtail[k]), dx * dx + dy * dy + dz * dz + dw * dw, acc);
    }

    // Warp reduction
    #pragma unroll
    for (int off = 16; off > 0; off >>= 1)
        acc += __shfl_down_sync(0xffffffffu, acc, off);

    __shared__ float warp_sums[8];
    int lane = threadIdx.x & 31;
    int wid  = threadIdx.x >> 5;
    if (lane == 0) warp_sums[wid] = acc;
    __syncthreads();

    __shared__ bool is_last;
    if (wid == 0) {
        float v = (lane < 8) ? warp_sums[lane] : 0.0f;
        #pragma unroll
        for (int off = 4; off > 0; off >>= 1)
            v += __shfl_down_sync(0xffffffffu, v, off);
        if (lane == 0) {
            g_partials[blockIdx.x] = v;
            __threadfence();
            unsigned int done = atomicInc(&g_ticket, gridDim.x - 1);
            is_last = (done == gridDim.x - 1);  // wraps to 0 on last -> ticket reset
        }
    }
    __syncthreads();

    // Last block reduces the per-block partials and writes the mean.
    if (is_last) {
        double s = 0.0;
        for (int i = threadIdx.x; i < (int)gridDim.x; i += blockDim.x)
            s += (double)g_partials[i];
        __shared__ double dsums[8];
        #pragma unroll
        for (int off = 16; off > 0; off >>= 1)
            s += __shfl_down_sync(0xffffffffu, s, off);
        if (lane == 0) dsums[wid] = s;
        __syncthreads();
        if (wid == 0) {
            double t = (lane < 8) ? dsums[lane] : 0.0;
            #pragma unroll
            for (int off = 4; off > 0; off >>= 1)
                t += __shfl_down_sync(0xffffffffu, t, off);
            if (lane == 0)
                out[0] = (float)(t * (double)inv_p);
        }
    }
}

extern "C" void kernel_launch(void* const* d_in, const int* in_sizes, int n_in,
                              void* d_out, int out_size) {
    // Inputs: X (f32, 1M x 4), edges (int32, 10M x 2), weights (f32, 10M)
    const float4* X     = (const float4*)d_in[0];
    const int*    edges = (const int*)d_in[1];
    const float*  w     = (const float*)d_in[2];
    float*        out   = (float*)d_out;

    int p = in_sizes[2];
    int npairs = p / 2;

    // ~4 waves: 4 x 148 SMs x 8 resident CTAs. Oversubscription amortizes the
    // cross-CTA completion spread (R2 evidence: 4883-block main kernel ~74us).
    const int threads = 256;
    long long want = ((long long)npairs + (long long)threads * 4 - 1) /
                     ((long long)threads * 4);   // ~4 pairs/thread min
    int blocks = 4736;
    if ((long long)blocks > want && want >= 1184) blocks = (int)want;
    if (blocks < 1184) blocks = 1184;            // never below one full wave
    if (blocks > MAX_BLOCKS) blocks = MAX_BLOCKS;

    mde_fused_kernel<<<blocks, threads>>>(
        X,
        (const int4*)edges, (const float2*)w, npairs,
        (const int2*)edges, w, p,
        out, 1.0f / (float)p);
}